// round 15
// baseline (speedup 1.0000x reference)
#include <cuda_runtime.h>
#include <cuda_fp16.h>
#include <cstdint>
#include <math.h>

#define N_NODES   100000
#define N_EDGES   1600000
#define HID       128
#define N_CLASSES 18
#define N_CENT    2
#define N_GRAPHS  512
#define PAD_ROWS  128

// ---------------- scratch (static device memory; no allocs allowed) ----------
// g_deg invariant: ZERO at entry to kernel_launch (zero-init at load; re-zeroed
// by pool_centroid_cleanup at the end of every call).
__device__ __half g_x16[(N_NODES + PAD_ROWS) * HID]; // X converted to fp16
__device__ __half g_hn [N_NODES * HID];              // h * dinv (gather source)
__device__ __half g_cur[(N_NODES + PAD_ROWS) * HID]; // layer output (fp16, padded)
__device__ float g_dinv[N_NODES];
__device__ int   g_deg [N_NODES];
__device__ int   g_off [N_NODES];
__device__ int   g_cursor[N_NODES];
__device__ int   g_csr [N_EDGES];
__device__ int   g_goff[N_GRAPHS + 1];
__device__ __half g_wth[3 * HID * HID];    // W^T hi  [layer][N][K] fp16
__device__ __half g_wtl[3 * HID * HID];    // W^T lo residual fp16

// ---------------- local int64/int32 detection (pure, per-block) --------------
static __device__ __forceinline__ int detect_e64(const void* ebuf) {
    const int* p = (const int*)ebuf;
    int nz = 0;
    #pragma unroll
    for (int i = 0; i < 8; i++) {
        long long k = 1000 + (long long)i * 997;
        if (p[2 * k + 1] != 0) nz++;
    }
    return nz < 4;
}
static __device__ __forceinline__ int detect_b64(const void* bbuf) {
    const int* p = (const int*)bbuf;
    int nz = 0;
    #pragma unroll
    for (int i = 0; i < 8; i++) {
        long long k = 20000 + (long long)i * 117;
        if (p[2 * k + 1] != 0) nz++;
    }
    return nz < 4;
}

// ---------------- L0: fused setup (X->fp16 | W split | bounds | deg) ---------
#define R_X (N_NODES * HID / 2)
#define R_W (3 * HID * HID)
#define R_B (N_NODES + 1)
#define R_E N_EDGES
#define R_TOT (R_X + R_W + R_B + R_E)

__global__ void setup_kernel(const float* __restrict__ x,
                             const float* __restrict__ W1,
                             const float* __restrict__ W2,
                             const float* __restrict__ W3,
                             const void* bbuf, const void* ebuf) {
    __shared__ int s_b64, s_e64;
    if (threadIdx.x == 0) { s_b64 = detect_b64(bbuf); s_e64 = detect_e64(ebuf); }
    __syncthreads();
    int i = blockIdx.x * blockDim.x + threadIdx.x;
    if (i < R_X) {
        float2 f = ((const float2*)x)[i];
        ((__half2*)g_x16)[i] = __floats2half2_rn(f.x, f.y);
        return;
    }
    if (i < R_X + R_W) {
        int j = i - R_X;
        int layer = j >> 14;
        int m = j & (HID * HID - 1);
        int k = m >> 7, ncol = m & 127;
        const float* W = (layer == 0) ? W1 : (layer == 1) ? W2 : W3;
        float w = W[m];
        __half hi = __float2half_rn(w);
        g_wth[layer * HID * HID + ncol * HID + k] = hi;
        g_wtl[layer * HID * HID + ncol * HID + k] = __float2half_rn(w - __half2float(hi));
        return;
    }
    if (i < R_X + R_W + R_B) {
        int j = i - (R_X + R_W);
        int bi = N_GRAPHS, bp = -1;
        if (s_b64) {
            const long long* p = (const long long*)bbuf;
            if (j < N_NODES) bi = (int)p[j];
            if (j > 0)       bp = (int)p[j - 1];
        } else {
            const int* p = (const int*)bbuf;
            if (j < N_NODES) bi = p[j];
            if (j > 0)       bp = p[j - 1];
        }
        for (int g = bp + 1; g <= bi; g++) g_goff[g] = j;
        return;
    }
    if (i < R_TOT) {
        int e = i - (R_X + R_W + R_B);
        int d;
        if (s_e64) d = (int)((const long long*)ebuf)[N_EDGES + e];
        else       d = ((const int*)ebuf)[N_EDGES + e];
        atomicAdd(&g_deg[d], 1);
    }
}

// ---------------- scan -> offsets + cursor + dinv ----------------------------
#define SCAN_T 1024
#define CHUNK  98
__global__ void node_scan_kernel() {
    __shared__ int wsum[32];
    int tid = threadIdx.x, lane = tid & 31, wid = tid >> 5;
    int start = tid * CHUNK;
    int csum = 0;
    for (int i = 0; i < CHUNK; i++) {
        int idx = start + i;
        if (idx < N_NODES) csum += g_deg[idx];
    }
    int v = csum;
    #pragma unroll
    for (int o = 1; o < 32; o <<= 1) { int t = __shfl_up_sync(0xffffffffu, v, o); if (lane >= o) v += t; }
    if (lane == 31) wsum[wid] = v;
    __syncthreads();
    if (wid == 0) {
        int w = wsum[lane];
        #pragma unroll
        for (int o = 1; o < 32; o <<= 1) { int t = __shfl_up_sync(0xffffffffu, w, o); if (lane >= o) w += t; }
        wsum[lane] = w;
    }
    __syncthreads();
    int run = v - csum + (wid > 0 ? wsum[wid - 1] : 0);
    for (int i = 0; i < CHUNK; i++) {
        int idx = start + i;
        if (idx < N_NODES) {
            int d = g_deg[idx];
            g_off[idx] = run;
            g_cursor[idx] = run;
            g_dinv[idx] = rsqrtf((float)d + 1.0f);
            run += d;
        }
    }
}

__global__ void csr_fill_kernel(const void* ebuf) {
    __shared__ int s_e64;
    if (threadIdx.x == 0) s_e64 = detect_e64(ebuf);
    __syncthreads();
    int e = blockIdx.x * blockDim.x + threadIdx.x;
    if (e >= N_EDGES) return;
    int s, d;
    if (s_e64) {
        const long long* p = (const long long*)ebuf;
        s = (int)p[e]; d = (int)p[N_EDGES + e];
    } else {
        const int* p = (const int*)ebuf;
        s = p[e]; d = p[N_EDGES + e];
    }
    int pos = atomicAdd(&g_cursor[d], 1);
    g_csr[pos] = s;
}

// ---------------- persistent cp.async pipelined GEMM (R13-proven, manual LDS)
#define AP 72
#define SLAB (128 * AP)
#define SLAB_B (SLAB * 2)
#define GEMM_SMEM (6 * SLAB_B)
#define GEMM_GRID 296

#define MMA_FP16(c, a0,a1,a2,a3, b0,b1) \
    asm volatile("mma.sync.aligned.m16n8k16.row.col.f32.f16.f16.f32 " \
        "{%0,%1,%2,%3}, {%4,%5,%6,%7}, {%8,%9}, {%0,%1,%2,%3};" \
        : "+f"((c)[0]), "+f"((c)[1]), "+f"((c)[2]), "+f"((c)[3]) \
        : "r"(a0), "r"(a1), "r"(a2), "r"(a3), "r"(b0), "r"(b1))

static __device__ __forceinline__ uint32_t smem_u32(const void* p) {
    uint32_t a;
    asm("{ .reg .u64 t; cvta.to.shared.u64 t, %1; cvt.u32.u64 %0, t; }"
        : "=r"(a) : "l"(p));
    return a;
}

static __device__ __forceinline__ void issue_A(uint32_t sbuf, const __half* X,
                                               int row0, int ch) {
    const char* base = (const char*)(X + (size_t)row0 * HID + ch * 64);
    int tid = threadIdx.x;
    #pragma unroll
    for (int i = 0; i < 4; i++) {
        int seg = tid + i * 256;
        int r = seg >> 3, sj = seg & 7;
        uint32_t dst = sbuf + r * (AP * 2) + sj * 16;
        const char* src = base + (size_t)r * (HID * 2) + sj * 16;
        asm volatile("cp.async.ca.shared.global [%0], [%1], 16;" :: "r"(dst), "l"(src));
    }
    asm volatile("cp.async.commit_group;");
}

__global__ void __launch_bounds__(256, 2)
gemm_mma_kernel(const __half* __restrict__ X,
                const __half* __restrict__ wth,
                const __half* __restrict__ wtl, int n) {
    extern __shared__ __half sm[];
    int tid = threadIdx.x;
    int wid = tid >> 5, lane = tid & 31;
    uint32_t uS = smem_u32(sm);
    uint32_t uA[2] = { uS + 4 * SLAB_B, uS + 5 * SLAB_B };

    #pragma unroll
    for (int rr = 0; rr < 16; rr++) {
        int r = wid * 16 + rr;
        ((uint32_t*)(sm + 0 * SLAB + r * AP))[lane] = ((const uint32_t*)(wth + r * HID))[lane];
        ((uint32_t*)(sm + 1 * SLAB + r * AP))[lane] = ((const uint32_t*)(wtl + r * HID))[lane];
        ((uint32_t*)(sm + 2 * SLAB + r * AP))[lane] = ((const uint32_t*)(wth + r * HID + 64))[lane];
        ((uint32_t*)(sm + 3 * SLAB + r * AP))[lane] = ((const uint32_t*)(wtl + r * HID + 64))[lane];
    }

    int tiles = (n + 127) >> 7;
    int t0 = blockIdx.x;
    if (t0 < tiles) issue_A(uA[0], X, t0 * 128, 0);
    int cur = 0;

    int arow = wid * 16 + (lane >> 2);
    int koff = (lane & 3) * 2;

    for (int t = t0; t < tiles; t += gridDim.x) {
        float acc[16][4];
        #pragma unroll
        for (int q = 0; q < 16; q++) {
            acc[q][0] = 0.f; acc[q][1] = 0.f; acc[q][2] = 0.f; acc[q][3] = 0.f;
        }

        #pragma unroll
        for (int ch = 0; ch < 2; ch++) {
            if (ch == 0) {
                issue_A(uA[cur ^ 1], X, t * 128, 1);
                asm volatile("cp.async.wait_group 1;");
            } else {
                int tn = t + gridDim.x;
                if (tn < tiles) {
                    issue_A(uA[cur ^ 1], X, tn * 128, 0);
                    asm volatile("cp.async.wait_group 1;");
                } else {
                    asm volatile("cp.async.wait_group 0;");
                }
            }
            __syncthreads();

            const __half* sA  = (const __half*)sm + (4 + cur) * SLAB;
            const __half* sWh = sm + (ch * 2 + 0) * SLAB;
            const __half* sWl = sm + (ch * 2 + 1) * SLAB;

            #pragma unroll
            for (int ks = 0; ks < 4; ks++) {
                int k = ks * 16;
                const __half* pA0 = sA + arow * AP + k + koff;
                uint32_t a0 = *(const uint32_t*)(pA0);
                uint32_t a1 = *(const uint32_t*)(pA0 + 8 * AP);
                uint32_t a2 = *(const uint32_t*)(pA0 + 8);
                uint32_t a3 = *(const uint32_t*)(pA0 + 8 * AP + 8);
                #pragma unroll
                for (int nt = 0; nt < 16; nt++) {
                    int brow = nt * 8 + (lane >> 2);
                    const __half* pBh = sWh + brow * AP + k + koff;
                    const __half* pBl = sWl + brow * AP + k + koff;
                    uint32_t bh0 = *(const uint32_t*)(pBh);
                    uint32_t bh1 = *(const uint32_t*)(pBh + 8);
                    uint32_t bl0 = *(const uint32_t*)(pBl);
                    uint32_t bl1 = *(const uint32_t*)(pBl + 8);
                    MMA_FP16(acc[nt], a0, a1, a2, a3, bh0, bh1);
                    MMA_FP16(acc[nt], a0, a1, a2, a3, bl0, bl1);
                }
            }
            __syncthreads();
            cur ^= 1;
        }

        int r0 = t * 128;
        int row0 = r0 + wid * 16 + (lane >> 2);
        int row1 = row0 + 8;
        float di0 = (row0 < n) ? rsqrtf((float)g_deg[row0] + 1.0f) : 0.f;
        float di1 = (row1 < n) ? rsqrtf((float)g_deg[row1] + 1.0f) : 0.f;
        int colb = (lane & 3) * 2;
        #pragma unroll
        for (int nt = 0; nt < 16; nt++) {
            int col = nt * 8 + colb;
            if (row0 < n)
                *(__half2*)(g_hn + (size_t)row0 * HID + col) =
                    __floats2half2_rn(acc[nt][0] * di0, acc[nt][1] * di0);
            if (row1 < n)
                *(__half2*)(g_hn + (size_t)row1 * HID + col) =
                    __floats2half2_rn(acc[nt][2] * di1, acc[nt][3] * di1);
        }
    }
}

// ---------------- aggregate v5: full fp16 reduction tree for 8-edge groups ---
// Per 8 edges: 8 LDG + 14 HADD2 + 2 cvt2 + 4 FADD  (v4: 8 LDG + 8 HADD2 + 16 cvt + 16 FADD)
#define AGG_BLOCKS 1184

static __device__ __forceinline__ void acc_pair(float4& sum, uint2 a, uint2 b) {
    __half2 h0 = __hadd2(*(__half2*)&a.x, *(__half2*)&b.x);
    __half2 h1 = __hadd2(*(__half2*)&a.y, *(__half2*)&b.y);
    float2 f0 = __half22float2(h0);
    float2 f1 = __half22float2(h1);
    sum.x += f0.x; sum.y += f0.y; sum.z += f1.x; sum.w += f1.y;
}
static __device__ __forceinline__ void acc_one(float4& sum, uint2 a) {
    float2 f0 = __half22float2(*(__half2*)&a.x);
    float2 f1 = __half22float2(*(__half2*)&a.y);
    sum.x += f0.x; sum.y += f0.y; sum.z += f1.x; sum.w += f1.y;
}

__global__ void aggregate_kernel(const float* __restrict__ bias, int do_relu) {
    int lane = threadIdx.x & 31;
    int wstride = (gridDim.x * blockDim.x) >> 5;
    const uint2* hn2 = (const uint2*)g_hn;     // 32 uint2 per row
    float4 bv = ((const float4*)bias)[lane];

    for (int w = (blockIdx.x * blockDim.x + threadIdx.x) >> 5; w < N_NODES; w += wstride) {
        float4 sum = make_float4(0.f, 0.f, 0.f, 0.f);
        acc_one(sum, hn2[(size_t)w * 32 + lane]);   // self loop
        int base = g_off[w];
        int cnt  = g_deg[w];
        int j = 0;
        for (; j + 8 <= cnt; j += 8) {
            int s0 = g_csr[base + j + 0];
            int s1 = g_csr[base + j + 1];
            int s2 = g_csr[base + j + 2];
            int s3 = g_csr[base + j + 3];
            int s4 = g_csr[base + j + 4];
            int s5 = g_csr[base + j + 5];
            int s6 = g_csr[base + j + 6];
            int s7 = g_csr[base + j + 7];
            uint2 v0 = hn2[(size_t)s0 * 32 + lane];
            uint2 v1 = hn2[(size_t)s1 * 32 + lane];
            uint2 v2 = hn2[(size_t)s2 * 32 + lane];
            uint2 v3 = hn2[(size_t)s3 * 32 + lane];
            uint2 v4 = hn2[(size_t)s4 * 32 + lane];
            uint2 v5 = hn2[(size_t)s5 * 32 + lane];
            uint2 v6 = hn2[(size_t)s6 * 32 + lane];
            uint2 v7 = hn2[(size_t)s7 * 32 + lane];
            // fp16 tree: level 1 (4 pairs)
            __half2 p0x = __hadd2(*(__half2*)&v0.x, *(__half2*)&v1.x);
            __half2 p0y = __hadd2(*(__half2*)&v0.y, *(__half2*)&v1.y);
            __half2 p1x = __hadd2(*(__half2*)&v2.x, *(__half2*)&v3.x);
            __half2 p1y = __hadd2(*(__half2*)&v2.y, *(__half2*)&v3.y);
            __half2 p2x = __hadd2(*(__half2*)&v4.x, *(__half2*)&v5.x);
            __half2 p2y = __hadd2(*(__half2*)&v4.y, *(__half2*)&v5.y);
            __half2 p3x = __hadd2(*(__half2*)&v6.x, *(__half2*)&v7.x);
            __half2 p3y = __hadd2(*(__half2*)&v6.y, *(__half2*)&v7.y);
            // level 2
            __half2 q0x = __hadd2(p0x, p1x);
            __half2 q0y = __hadd2(p0y, p1y);
            __half2 q1x = __hadd2(p2x, p3x);
            __half2 q1y = __hadd2(p2y, p3y);
            // level 3
            __half2 rx = __hadd2(q0x, q1x);
            __half2 ry = __hadd2(q0y, q1y);
            float2 f0 = __half22float2(rx);
            float2 f1 = __half22float2(ry);
            sum.x += f0.x; sum.y += f0.y; sum.z += f1.x; sum.w += f1.y;
        }
        for (; j + 2 <= cnt; j += 2) {
            int s0 = g_csr[base + j + 0];
            int s1 = g_csr[base + j + 1];
            uint2 v0 = hn2[(size_t)s0 * 32 + lane];
            uint2 v1 = hn2[(size_t)s1 * 32 + lane];
            acc_pair(sum, v0, v1);
        }
        if (j < cnt) {
            int s = g_csr[base + j];
            acc_one(sum, hn2[(size_t)s * 32 + lane]);
        }

        float di = g_dinv[w];
        float o0 = sum.x * di + bv.x, o1 = sum.y * di + bv.y;
        float o2 = sum.z * di + bv.z, o3 = sum.w * di + bv.w;
        if (do_relu) {
            o0 = fmaxf(o0, 0.f); o1 = fmaxf(o1, 0.f);
            o2 = fmaxf(o2, 0.f); o3 = fmaxf(o3, 0.f);
        }
        __half2 h0 = __floats2half2_rn(o0, o1);
        __half2 h1 = __floats2half2_rn(o2, o3);
        uint2 st;
        st.x = *(uint32_t*)&h0;
        st.y = *(uint32_t*)&h1;
        ((uint2*)g_cur)[(size_t)w * 32 + lane] = st;
    }
}

// ---------------- fused pooling + centroid head + cleanup --------------------
__global__ void pool_centroid_cleanup_kernel(const float* __restrict__ cent,
                                             const float* __restrict__ ac_temp,
                                             float* __restrict__ out) {
    int b = blockIdx.x;
    int tid = threadIdx.x;            // 128 threads
    int lane = tid & 31, w = tid >> 5;
    __shared__ float sd[N_CLASSES * N_CENT];
    __shared__ float sg[HID];

    // restore invariant: g_deg = 0 for next kernel_launch call
    int total = gridDim.x * blockDim.x;
    for (int z = b * blockDim.x + tid; z < N_NODES; z += total) g_deg[z] = 0;

    int s = g_goff[b], e = g_goff[b + 1];
    float sum = 0.f;
    for (int r = s; r < e; r++) sum += __half2float(g_cur[(size_t)r * HID + tid]);
    sg[tid] = sum / fmaxf((float)(e - s), 1.0f);
    __syncthreads();

    for (int p = w; p < N_CLASSES * N_CENT; p += 4) {
        const float* cp = cent + p * HID;
        float ss = 0.f;
        #pragma unroll
        for (int q = 0; q < 4; q++) {
            float d = cp[lane + q * 32] - sg[lane + q * 32];
            ss = fmaf(d, d, ss);
        }
        #pragma unroll
        for (int o = 16; o; o >>= 1) ss += __shfl_xor_sync(0xffffffffu, ss, o);
        if (lane == 0) sd[p] = sqrtf(ss);
    }
    __syncthreads();
    if (tid == 0) {
        float mind = 1e30f;
        #pragma unroll
        for (int c = 0; c < N_CLASSES; c++) {
            float d = fminf(sd[2 * c], sd[2 * c + 1]);
            out[b * N_CLASSES + c] = -d;
            mind = fminf(mind, d);
        }
        float accept = 1.0f - mind;   // RUNNING_VAR==0 => max_ac==1.0
        float t = ac_temp[0];
        out[N_GRAPHS * N_CLASSES + b] = 1.0f / (1.0f + expf(-accept / t));
    }
}

// ---------------- launch ----------------------------------------------------
extern "C" void kernel_launch(void* const* d_in, const int* in_sizes, int n_in,
                              void* d_out, int out_size) {
    const float* x     = (const float*)d_in[0];
    const void*  edges = d_in[1];
    const void*  batch = d_in[2];
    const float* W1 = (const float*)d_in[3];
    const float* b1 = (const float*)d_in[4];
    const float* W2 = (const float*)d_in[5];
    const float* b2 = (const float*)d_in[6];
    const float* W3 = (const float*)d_in[7];
    const float* b3 = (const float*)d_in[8];
    const float* cent = (const float*)d_in[9];
    const float* ac_temp = (const float*)d_in[11];
    float* out = (float*)d_out;

    cudaFuncSetAttribute(gemm_mma_kernel, cudaFuncAttributeMaxDynamicSharedMemorySize, GEMM_SMEM);

    __half *wth_p, *wtl_p, *cur_p, *x16_p;
    cudaGetSymbolAddress((void**)&wth_p, g_wth);
    cudaGetSymbolAddress((void**)&wtl_p, g_wtl);
    cudaGetSymbolAddress((void**)&cur_p, g_cur);
    cudaGetSymbolAddress((void**)&x16_p, g_x16);

    int setup_blocks = (R_TOT + 255) / 256;

    setup_kernel<<<setup_blocks, 256>>>(x, W1, W2, W3, batch, edges);        // 0
    node_scan_kernel<<<1, SCAN_T>>>();                                       // 1
    csr_fill_kernel<<<(N_EDGES + 255) / 256, 256>>>(edges);                  // 2
    gemm_mma_kernel<<<GEMM_GRID, 256, GEMM_SMEM>>>(x16_p, wth_p, wtl_p, N_NODES); // 3 <- profiled
    aggregate_kernel<<<AGG_BLOCKS, 256>>>(b1, 1);                            // 4
    gemm_mma_kernel<<<GEMM_GRID, 256, GEMM_SMEM>>>(cur_p, wth_p + HID * HID, wtl_p + HID * HID, N_NODES); // 5
    aggregate_kernel<<<AGG_BLOCKS, 256>>>(b2, 1);                            // 6
    gemm_mma_kernel<<<GEMM_GRID, 256, GEMM_SMEM>>>(cur_p, wth_p + 2 * HID * HID, wtl_p + 2 * HID * HID, N_NODES); // 7
    aggregate_kernel<<<AGG_BLOCKS, 256>>>(b3, 0);                            // 8
    pool_centroid_cleanup_kernel<<<N_GRAPHS, HID>>>(cent, ac_temp, out);     // 9
}

// round 16
// speedup vs baseline: 1.1022x; 1.1022x over previous
#include <cuda_runtime.h>
#include <cuda_fp16.h>
#include <cstdint>
#include <math.h>

#define N_NODES   100000
#define N_EDGES   1600000
#define HID       128
#define N_CLASSES 18
#define N_CENT    2
#define N_GRAPHS  512
#define PAD_ROWS  128

// ---------------- scratch (static device memory; no allocs allowed) ----------
// g_deg invariant: ZERO at entry to kernel_launch (zero-init at load; re-zeroed
// by pool_centroid_cleanup at the end of every call).
__device__ __half g_x16[(N_NODES + PAD_ROWS) * HID]; // X converted to fp16
__device__ __half g_hn [N_NODES * HID];              // h * dinv (gather source)
__device__ __half g_cur[(N_NODES + PAD_ROWS) * HID]; // layer output (fp16, padded)
__device__ float g_dinv[N_NODES];
__device__ int   g_deg [N_NODES];
__device__ int   g_off [N_NODES];
__device__ int   g_cursor[N_NODES];
__device__ int   g_csr [N_EDGES];
__device__ int   g_goff[N_GRAPHS + 1];
__device__ __half g_wth[3 * HID * HID];    // W^T hi  [layer][N][K] fp16
__device__ __half g_wtl[3 * HID * HID];    // W^T lo residual fp16

// ---------------- local int64/int32 detection (pure, per-block) --------------
static __device__ __forceinline__ int detect_e64(const void* ebuf) {
    const int* p = (const int*)ebuf;
    int nz = 0;
    #pragma unroll
    for (int i = 0; i < 8; i++) {
        long long k = 1000 + (long long)i * 997;
        if (p[2 * k + 1] != 0) nz++;
    }
    return nz < 4;
}
static __device__ __forceinline__ int detect_b64(const void* bbuf) {
    const int* p = (const int*)bbuf;
    int nz = 0;
    #pragma unroll
    for (int i = 0; i < 8; i++) {
        long long k = 20000 + (long long)i * 117;
        if (p[2 * k + 1] != 0) nz++;
    }
    return nz < 4;
}

// ---------------- L0: fused setup (X->fp16 | W split | bounds | deg) ---------
#define R_X (N_NODES * HID / 2)
#define R_W (3 * HID * HID)
#define R_B (N_NODES + 1)
#define R_E N_EDGES
#define R_TOT (R_X + R_W + R_B + R_E)

__global__ void setup_kernel(const float* __restrict__ x,
                             const float* __restrict__ W1,
                             const float* __restrict__ W2,
                             const float* __restrict__ W3,
                             const void* bbuf, const void* ebuf) {
    __shared__ int s_b64, s_e64;
    if (threadIdx.x == 0) { s_b64 = detect_b64(bbuf); s_e64 = detect_e64(ebuf); }
    __syncthreads();
    int i = blockIdx.x * blockDim.x + threadIdx.x;
    if (i < R_X) {
        float2 f = ((const float2*)x)[i];
        ((__half2*)g_x16)[i] = __floats2half2_rn(f.x, f.y);
        return;
    }
    if (i < R_X + R_W) {
        int j = i - R_X;
        int layer = j >> 14;
        int m = j & (HID * HID - 1);
        int k = m >> 7, ncol = m & 127;
        const float* W = (layer == 0) ? W1 : (layer == 1) ? W2 : W3;
        float w = W[m];
        __half hi = __float2half_rn(w);
        g_wth[layer * HID * HID + ncol * HID + k] = hi;
        g_wtl[layer * HID * HID + ncol * HID + k] = __float2half_rn(w - __half2float(hi));
        return;
    }
    if (i < R_X + R_W + R_B) {
        int j = i - (R_X + R_W);
        int bi = N_GRAPHS, bp = -1;
        if (s_b64) {
            const long long* p = (const long long*)bbuf;
            if (j < N_NODES) bi = (int)p[j];
            if (j > 0)       bp = (int)p[j - 1];
        } else {
            const int* p = (const int*)bbuf;
            if (j < N_NODES) bi = p[j];
            if (j > 0)       bp = p[j - 1];
        }
        for (int g = bp + 1; g <= bi; g++) g_goff[g] = j;
        return;
    }
    if (i < R_TOT) {
        int e = i - (R_X + R_W + R_B);
        int d;
        if (s_e64) d = (int)((const long long*)ebuf)[N_EDGES + e];
        else       d = ((const int*)ebuf)[N_EDGES + e];
        atomicAdd(&g_deg[d], 1);
    }
}

// ---------------- scan -> offsets + cursor + dinv ----------------------------
#define SCAN_T 1024
#define CHUNK  98
__global__ void node_scan_kernel() {
    __shared__ int wsum[32];
    int tid = threadIdx.x, lane = tid & 31, wid = tid >> 5;
    int start = tid * CHUNK;
    int csum = 0;
    for (int i = 0; i < CHUNK; i++) {
        int idx = start + i;
        if (idx < N_NODES) csum += g_deg[idx];
    }
    int v = csum;
    #pragma unroll
    for (int o = 1; o < 32; o <<= 1) { int t = __shfl_up_sync(0xffffffffu, v, o); if (lane >= o) v += t; }
    if (lane == 31) wsum[wid] = v;
    __syncthreads();
    if (wid == 0) {
        int w = wsum[lane];
        #pragma unroll
        for (int o = 1; o < 32; o <<= 1) { int t = __shfl_up_sync(0xffffffffu, w, o); if (lane >= o) w += t; }
        wsum[lane] = w;
    }
    __syncthreads();
    int run = v - csum + (wid > 0 ? wsum[wid - 1] : 0);
    for (int i = 0; i < CHUNK; i++) {
        int idx = start + i;
        if (idx < N_NODES) {
            int d = g_deg[idx];
            g_off[idx] = run;
            g_cursor[idx] = run;
            g_dinv[idx] = rsqrtf((float)d + 1.0f);
            run += d;
        }
    }
}

__global__ void csr_fill_kernel(const void* ebuf) {
    __shared__ int s_e64;
    if (threadIdx.x == 0) s_e64 = detect_e64(ebuf);
    __syncthreads();
    int e = blockIdx.x * blockDim.x + threadIdx.x;
    if (e >= N_EDGES) return;
    int s, d;
    if (s_e64) {
        const long long* p = (const long long*)ebuf;
        s = (int)p[e]; d = (int)p[N_EDGES + e];
    } else {
        const int* p = (const int*)ebuf;
        s = p[e]; d = p[N_EDGES + e];
    }
    int pos = atomicAdd(&g_cursor[d], 1);
    g_csr[pos] = s;
}

// ---------------- persistent cp.async pipelined GEMM (R13-proven, manual LDS)
#define AP 72
#define SLAB (128 * AP)
#define SLAB_B (SLAB * 2)
#define GEMM_SMEM (6 * SLAB_B)
#define GEMM_GRID 296

#define MMA_FP16(c, a0,a1,a2,a3, b0,b1) \
    asm volatile("mma.sync.aligned.m16n8k16.row.col.f32.f16.f16.f32 " \
        "{%0,%1,%2,%3}, {%4,%5,%6,%7}, {%8,%9}, {%0,%1,%2,%3};" \
        : "+f"((c)[0]), "+f"((c)[1]), "+f"((c)[2]), "+f"((c)[3]) \
        : "r"(a0), "r"(a1), "r"(a2), "r"(a3), "r"(b0), "r"(b1))

static __device__ __forceinline__ uint32_t smem_u32(const void* p) {
    uint32_t a;
    asm("{ .reg .u64 t; cvta.to.shared.u64 t, %1; cvt.u32.u64 %0, t; }"
        : "=r"(a) : "l"(p));
    return a;
}

static __device__ __forceinline__ void issue_A(uint32_t sbuf, const __half* X,
                                               int row0, int ch) {
    const char* base = (const char*)(X + (size_t)row0 * HID + ch * 64);
    int tid = threadIdx.x;
    #pragma unroll
    for (int i = 0; i < 4; i++) {
        int seg = tid + i * 256;
        int r = seg >> 3, sj = seg & 7;
        uint32_t dst = sbuf + r * (AP * 2) + sj * 16;
        const char* src = base + (size_t)r * (HID * 2) + sj * 16;
        asm volatile("cp.async.ca.shared.global [%0], [%1], 16;" :: "r"(dst), "l"(src));
    }
    asm volatile("cp.async.commit_group;");
}

__global__ void __launch_bounds__(256, 2)
gemm_mma_kernel(const __half* __restrict__ X,
                const __half* __restrict__ wth,
                const __half* __restrict__ wtl, int n) {
    extern __shared__ __half sm[];
    int tid = threadIdx.x;
    int wid = tid >> 5, lane = tid & 31;
    uint32_t uS = smem_u32(sm);
    uint32_t uA[2] = { uS + 4 * SLAB_B, uS + 5 * SLAB_B };

    #pragma unroll
    for (int rr = 0; rr < 16; rr++) {
        int r = wid * 16 + rr;
        ((uint32_t*)(sm + 0 * SLAB + r * AP))[lane] = ((const uint32_t*)(wth + r * HID))[lane];
        ((uint32_t*)(sm + 1 * SLAB + r * AP))[lane] = ((const uint32_t*)(wtl + r * HID))[lane];
        ((uint32_t*)(sm + 2 * SLAB + r * AP))[lane] = ((const uint32_t*)(wth + r * HID + 64))[lane];
        ((uint32_t*)(sm + 3 * SLAB + r * AP))[lane] = ((const uint32_t*)(wtl + r * HID + 64))[lane];
    }

    int tiles = (n + 127) >> 7;
    int t0 = blockIdx.x;
    if (t0 < tiles) issue_A(uA[0], X, t0 * 128, 0);
    int cur = 0;

    int arow = wid * 16 + (lane >> 2);
    int koff = (lane & 3) * 2;

    for (int t = t0; t < tiles; t += gridDim.x) {
        float acc[16][4];
        #pragma unroll
        for (int q = 0; q < 16; q++) {
            acc[q][0] = 0.f; acc[q][1] = 0.f; acc[q][2] = 0.f; acc[q][3] = 0.f;
        }

        #pragma unroll
        for (int ch = 0; ch < 2; ch++) {
            if (ch == 0) {
                issue_A(uA[cur ^ 1], X, t * 128, 1);
                asm volatile("cp.async.wait_group 1;");
            } else {
                int tn = t + gridDim.x;
                if (tn < tiles) {
                    issue_A(uA[cur ^ 1], X, tn * 128, 0);
                    asm volatile("cp.async.wait_group 1;");
                } else {
                    asm volatile("cp.async.wait_group 0;");
                }
            }
            __syncthreads();

            const __half* sA  = (const __half*)sm + (4 + cur) * SLAB;
            const __half* sWh = sm + (ch * 2 + 0) * SLAB;
            const __half* sWl = sm + (ch * 2 + 1) * SLAB;

            #pragma unroll
            for (int ks = 0; ks < 4; ks++) {
                int k = ks * 16;
                const __half* pA0 = sA + arow * AP + k + koff;
                uint32_t a0 = *(const uint32_t*)(pA0);
                uint32_t a1 = *(const uint32_t*)(pA0 + 8 * AP);
                uint32_t a2 = *(const uint32_t*)(pA0 + 8);
                uint32_t a3 = *(const uint32_t*)(pA0 + 8 * AP + 8);
                #pragma unroll
                for (int nt = 0; nt < 16; nt++) {
                    int brow = nt * 8 + (lane >> 2);
                    const __half* pBh = sWh + brow * AP + k + koff;
                    const __half* pBl = sWl + brow * AP + k + koff;
                    uint32_t bh0 = *(const uint32_t*)(pBh);
                    uint32_t bh1 = *(const uint32_t*)(pBh + 8);
                    uint32_t bl0 = *(const uint32_t*)(pBl);
                    uint32_t bl1 = *(const uint32_t*)(pBl + 8);
                    MMA_FP16(acc[nt], a0, a1, a2, a3, bh0, bh1);
                    MMA_FP16(acc[nt], a0, a1, a2, a3, bl0, bl1);
                }
            }
            __syncthreads();
            cur ^= 1;
        }

        int r0 = t * 128;
        int row0 = r0 + wid * 16 + (lane >> 2);
        int row1 = row0 + 8;
        float di0 = (row0 < n) ? rsqrtf((float)g_deg[row0] + 1.0f) : 0.f;
        float di1 = (row1 < n) ? rsqrtf((float)g_deg[row1] + 1.0f) : 0.f;
        int colb = (lane & 3) * 2;
        #pragma unroll
        for (int nt = 0; nt < 16; nt++) {
            int col = nt * 8 + colb;
            if (row0 < n)
                *(__half2*)(g_hn + (size_t)row0 * HID + col) =
                    __floats2half2_rn(acc[nt][0] * di0, acc[nt][1] * di0);
            if (row1 < n)
                *(__half2*)(g_hn + (size_t)row1 * HID + col) =
                    __floats2half2_rn(acc[nt][2] * di1, acc[nt][3] * di1);
        }
    }
}

// ---------------- aggregate v4 (R13-proven): fp16 pairwise pre-add -----------
#define AGG_BLOCKS 1184

static __device__ __forceinline__ void acc_pair(float4& sum, uint2 a, uint2 b) {
    __half2 h0 = __hadd2(*(__half2*)&a.x, *(__half2*)&b.x);
    __half2 h1 = __hadd2(*(__half2*)&a.y, *(__half2*)&b.y);
    float2 f0 = __half22float2(h0);
    float2 f1 = __half22float2(h1);
    sum.x += f0.x; sum.y += f0.y; sum.z += f1.x; sum.w += f1.y;
}
static __device__ __forceinline__ void acc_one(float4& sum, uint2 a) {
    float2 f0 = __half22float2(*(__half2*)&a.x);
    float2 f1 = __half22float2(*(__half2*)&a.y);
    sum.x += f0.x; sum.y += f0.y; sum.z += f1.x; sum.w += f1.y;
}

__global__ void aggregate_kernel(const float* __restrict__ bias, int do_relu) {
    int lane = threadIdx.x & 31;
    int wstride = (gridDim.x * blockDim.x) >> 5;
    const uint2* hn2 = (const uint2*)g_hn;     // 32 uint2 per row
    float4 bv = ((const float4*)bias)[lane];

    for (int w = (blockIdx.x * blockDim.x + threadIdx.x) >> 5; w < N_NODES; w += wstride) {
        float4 sum = make_float4(0.f, 0.f, 0.f, 0.f);
        acc_one(sum, hn2[(size_t)w * 32 + lane]);   // self loop
        int base = g_off[w];
        int cnt  = g_deg[w];
        int j = 0;
        for (; j + 8 <= cnt; j += 8) {
            int s0 = g_csr[base + j + 0];
            int s1 = g_csr[base + j + 1];
            int s2 = g_csr[base + j + 2];
            int s3 = g_csr[base + j + 3];
            int s4 = g_csr[base + j + 4];
            int s5 = g_csr[base + j + 5];
            int s6 = g_csr[base + j + 6];
            int s7 = g_csr[base + j + 7];
            uint2 v0 = hn2[(size_t)s0 * 32 + lane];
            uint2 v1 = hn2[(size_t)s1 * 32 + lane];
            uint2 v2 = hn2[(size_t)s2 * 32 + lane];
            uint2 v3 = hn2[(size_t)s3 * 32 + lane];
            uint2 v4 = hn2[(size_t)s4 * 32 + lane];
            uint2 v5 = hn2[(size_t)s5 * 32 + lane];
            uint2 v6 = hn2[(size_t)s6 * 32 + lane];
            uint2 v7 = hn2[(size_t)s7 * 32 + lane];
            acc_pair(sum, v0, v1);
            acc_pair(sum, v2, v3);
            acc_pair(sum, v4, v5);
            acc_pair(sum, v6, v7);
        }
        for (; j + 2 <= cnt; j += 2) {
            int s0 = g_csr[base + j + 0];
            int s1 = g_csr[base + j + 1];
            uint2 v0 = hn2[(size_t)s0 * 32 + lane];
            uint2 v1 = hn2[(size_t)s1 * 32 + lane];
            acc_pair(sum, v0, v1);
        }
        if (j < cnt) {
            int s = g_csr[base + j];
            acc_one(sum, hn2[(size_t)s * 32 + lane]);
        }

        float di = g_dinv[w];
        float o0 = sum.x * di + bv.x, o1 = sum.y * di + bv.y;
        float o2 = sum.z * di + bv.z, o3 = sum.w * di + bv.w;
        if (do_relu) {
            o0 = fmaxf(o0, 0.f); o1 = fmaxf(o1, 0.f);
            o2 = fmaxf(o2, 0.f); o3 = fmaxf(o3, 0.f);
        }
        __half2 h0 = __floats2half2_rn(o0, o1);
        __half2 h1 = __floats2half2_rn(o2, o3);
        uint2 st;
        st.x = *(uint32_t*)&h0;
        st.y = *(uint32_t*)&h1;
        ((uint2*)g_cur)[(size_t)w * 32 + lane] = st;
    }
}

// ---------------- fused pooling + centroid head + cleanup --------------------
__global__ void pool_centroid_cleanup_kernel(const float* __restrict__ cent,
                                             const float* __restrict__ ac_temp,
                                             float* __restrict__ out) {
    int b = blockIdx.x;
    int tid = threadIdx.x;            // 128 threads
    int lane = tid & 31, w = tid >> 5;
    __shared__ float sd[N_CLASSES * N_CENT];
    __shared__ float sg[HID];

    // restore invariant: g_deg = 0 for next kernel_launch call
    int total = gridDim.x * blockDim.x;
    for (int z = b * blockDim.x + tid; z < N_NODES; z += total) g_deg[z] = 0;

    int s = g_goff[b], e = g_goff[b + 1];
    float sum = 0.f;
    for (int r = s; r < e; r++) sum += __half2float(g_cur[(size_t)r * HID + tid]);
    sg[tid] = sum / fmaxf((float)(e - s), 1.0f);
    __syncthreads();

    for (int p = w; p < N_CLASSES * N_CENT; p += 4) {
        const float* cp = cent + p * HID;
        float ss = 0.f;
        #pragma unroll
        for (int q = 0; q < 4; q++) {
            float d = cp[lane + q * 32] - sg[lane + q * 32];
            ss = fmaf(d, d, ss);
        }
        #pragma unroll
        for (int o = 16; o; o >>= 1) ss += __shfl_xor_sync(0xffffffffu, ss, o);
        if (lane == 0) sd[p] = sqrtf(ss);
    }
    __syncthreads();
    if (tid == 0) {
        float mind = 1e30f;
        #pragma unroll
        for (int c = 0; c < N_CLASSES; c++) {
            float d = fminf(sd[2 * c], sd[2 * c + 1]);
            out[b * N_CLASSES + c] = -d;
            mind = fminf(mind, d);
        }
        float accept = 1.0f - mind;   // RUNNING_VAR==0 => max_ac==1.0
        float t = ac_temp[0];
        out[N_GRAPHS * N_CLASSES + b] = 1.0f / (1.0f + expf(-accept / t));
    }
}

// ---------------- launch (stream fork: csr build || gemm1) -------------------
extern "C" void kernel_launch(void* const* d_in, const int* in_sizes, int n_in,
                              void* d_out, int out_size) {
    const float* x     = (const float*)d_in[0];
    const void*  edges = d_in[1];
    const void*  batch = d_in[2];
    const float* W1 = (const float*)d_in[3];
    const float* b1 = (const float*)d_in[4];
    const float* W2 = (const float*)d_in[5];
    const float* b2 = (const float*)d_in[6];
    const float* W3 = (const float*)d_in[7];
    const float* b3 = (const float*)d_in[8];
    const float* cent = (const float*)d_in[9];
    const float* ac_temp = (const float*)d_in[11];
    float* out = (float*)d_out;

    cudaFuncSetAttribute(gemm_mma_kernel, cudaFuncAttributeMaxDynamicSharedMemorySize, GEMM_SMEM);

    __half *wth_p, *wtl_p, *cur_p, *x16_p;
    cudaGetSymbolAddress((void**)&wth_p, g_wth);
    cudaGetSymbolAddress((void**)&wtl_p, g_wtl);
    cudaGetSymbolAddress((void**)&cur_p, g_cur);
    cudaGetSymbolAddress((void**)&x16_p, g_x16);

    // static side stream + events: created once on first (uncaptured) call,
    // reused on every call -> identical captured work each time, no allocs in
    // the captured region itself.
    static cudaStream_t s2 = nullptr;
    static cudaEvent_t ev_fork = nullptr, ev_join = nullptr;
    if (s2 == nullptr) {
        cudaStreamCreateWithFlags(&s2, cudaStreamNonBlocking);
        cudaEventCreateWithFlags(&ev_fork, cudaEventDisableTiming);
        cudaEventCreateWithFlags(&ev_join, cudaEventDisableTiming);
    }

    int setup_blocks = (R_TOT + 255) / 256;

    setup_kernel<<<setup_blocks, 256>>>(x, W1, W2, W3, batch, edges);        // 0
    cudaEventRecord(ev_fork, 0);
    cudaStreamWaitEvent(s2, ev_fork, 0);
    node_scan_kernel<<<1, SCAN_T, 0, s2>>>();                                // 1 (s2)
    csr_fill_kernel<<<(N_EDGES + 255) / 256, 256, 0, s2>>>(edges);           // 2 (s2)
    cudaEventRecord(ev_join, s2);
    gemm_mma_kernel<<<GEMM_GRID, 256, GEMM_SMEM>>>(x16_p, wth_p, wtl_p, N_NODES); // 3 <- profiled (parallel with s2)
    cudaStreamWaitEvent(0, ev_join, 0);
    aggregate_kernel<<<AGG_BLOCKS, 256>>>(b1, 1);                            // 4
    gemm_mma_kernel<<<GEMM_GRID, 256, GEMM_SMEM>>>(cur_p, wth_p + HID * HID, wtl_p + HID * HID, N_NODES); // 5
    aggregate_kernel<<<AGG_BLOCKS, 256>>>(b2, 1);                            // 6
    gemm_mma_kernel<<<GEMM_GRID, 256, GEMM_SMEM>>>(cur_p, wth_p + 2 * HID * HID, wtl_p + 2 * HID * HID, N_NODES); // 7
    aggregate_kernel<<<AGG_BLOCKS, 256>>>(b3, 0);                            // 8
    pool_centroid_cleanup_kernel<<<N_GRAPHS, HID>>>(cent, ac_temp, out);     // 9
}